// round 17
// baseline (speedup 1.0000x reference)
#include <cuda_runtime.h>
#include <math.h>

#define NPTS 16384
#define DIM  64
#define NC   9
#define CAP  16384   // per-class region capacity
#define IT   64      // i-tile (= block size: 1 thread per i-row)
#define JT   16      // j-tile rows staged in smem
#define RATIO 4      // IT/JT
#define NB3  1184    // KB grid (8 per SM, one wave)
#define KAB  128     // KA blocks (128 x 128 = 16384 threads)

typedef unsigned long long u64;

// packed f32x2 fma: acc = a*b + acc (elementwise on 2 packed floats)
#define FMA2(acc, a, b) \
    asm("fma.rn.f32x2 %0, %1, %2, %3;" : "=l"(acc) : "l"(a), "l"(b), "l"(acc))

__device__ __forceinline__ float sum2(u64 v) {
    float2 f = *(float2*)&v;
    return f.x + f.y;
}

// ---- device scratch ----
__device__ float g_cf[8 * CAP * DIM];    // class-region normalized feats
__device__ int   g_fill[NC] = {0, 0, CAP, 2*CAP, 3*CAP, 4*CAP, 5*CAP, 6*CAP, 7*CAP};
__device__ float g_sum[NC * DIM];        // per-class normalized-feature sums
__device__ float g_cross[NC * NC];       // UNORDERED relu(dot) sums per class pair

// ---- KA: speculative-load classify + direct scatter + smem g_sum ----
__global__ void __launch_bounds__(128) ka_classify_scatter(
        const int* __restrict__ labels,
        const float* __restrict__ feats,
        const float* __restrict__ scores) {
    __shared__ int   hist[NC];
    __shared__ int   cbase[NC];
    __shared__ float ssum[NC * DIM];   // per-block class sums (2.3 KB)

    int tid = threadIdx.x;
    for (int i = tid; i < NC * DIM; i += 128) ssum[i] = 0.f;
    if (tid < NC) hist[tid] = 0;
    __syncthreads();

    int p = blockIdx.x * 128 + tid;

    // speculative: scores AND own feats row issued together (one mem latency)
    const float* sr = scores + p * NC;
    const float4* fr = (const float4*)(feats + p * DIM);
    float sv[NC];
    float4 v[16];
    #pragma unroll
    for (int c = 0; c < NC; c++) sv[c] = __ldg(&sr[c]);
    #pragma unroll
    for (int q = 0; q < 16; q++) v[q] = __ldg(&fr[q]);

    float mv = sv[0]; int mi = 0;
    #pragma unroll
    for (int c = 1; c < NC; c++) if (sv[c] > mv) { mv = sv[c]; mi = c; }
    float e = 0.f;
    #pragma unroll
    for (int c = 0; c < NC; c++) e += expf(sv[c] - mv);
    float pmax = 1.0f / e;

    int lab = labels[p];
    int cls = (lab == mi && pmax >= 0.5f && lab >= 1) ? lab : 0;

    int rank = 0;
    if (cls > 0) rank = atomicAdd(&hist[cls], 1);
    __syncthreads();
    if (tid >= 1 && tid < NC) {
        int h = hist[tid];
        if (h > 0) cbase[tid] = atomicAdd(&g_fill[tid], h);   // ONE atomic/class/block
    }
    __syncthreads();

    if (cls > 0) {
        float ss = 0.f;
        #pragma unroll
        for (int q = 0; q < 16; q++)
            ss += v[q].x * v[q].x + v[q].y * v[q].y + v[q].z * v[q].z + v[q].w * v[q].w;
        float inv = 1.0f / fmaxf(sqrtf(ss), 1e-12f);

        int slot = cbase[cls] + rank;
        float4* dst = (float4*)(g_cf + slot * DIM);
        float* sb = &ssum[cls * DIM];
        #pragma unroll
        for (int k = 0; k < 16; k++) {
            int q = (k + tid) & 15;    // lane-rotated: spreads smem banks
            float4 w = make_float4(v[q].x * inv, v[q].y * inv,
                                   v[q].z * inv, v[q].w * inv);
            dst[q] = w;
            atomicAdd(&sb[q * 4 + 0], w.x);
            atomicAdd(&sb[q * 4 + 1], w.y);
            atomicAdd(&sb[q * 4 + 2], w.z);
            atomicAdd(&sb[q * 4 + 3], w.w);
        }
    }
    __syncthreads();

    // flush block sums (512 spread addresses, fire-and-forget)
    for (int i = tid; i < NC * DIM; i += 128) {
        float s = ssum[i];
        if (s != 0.f) atomicAdd(&g_sum[i], s);
    }
}

// ---- KB: triangular pairwise relu(dot); no ticket, no finalize ----
__global__ void __launch_bounds__(64, 8) kb_pairs() {
    __shared__ ulonglong2 Js[JT][17];   // pitch 17: conflict-free, 16B aligned
    __shared__ float  scross[NC * NC];

    int tid = threadIdx.x;
    for (int i = tid; i < NC * NC; i += 64) scross[i] = 0.f;

    // per-thread register prefix (9 broadcast LDGs; no smem, no sync)
    int pre[NC + 1];
    pre[1] = 0;
    #pragma unroll
    for (int c = 1; c < NC; c++)
        pre[c + 1] = pre[c] + (__ldg(&g_fill[c]) - (c - 1) * CAP);
    int nv = pre[NC];

    int nit = (nv + IT - 1) / IT;
    int njt = (nv + JT - 1) / JT;
    int njobs = nit * njt - RATIO * nit * (nit - 1) / 2;

    const ulonglong2* cfp = (const ulonglong2*)g_cf;   // 16 per row

    for (int job = blockIdx.x; job < njobs; job += NB3) {
        int it = 0, rem = job;
        while (rem >= njt - RATIO * it) { rem -= njt - RATIO * it; it++; }
        int jt = RATIO * it + rem;
        int jb = jt * JT;

        int iv = it * IT + tid;
        int ci = 1, istart = 0;
        #pragma unroll
        for (int cc = 2; cc < NC; cc++)
            if (iv >= pre[cc]) { ci = cc; istart = pre[cc]; }
        int iphys = (ci - 1) * CAP + (iv - istart);
        if (iv >= nv) ci = 0;

        u64 rowp[32];
        #pragma unroll
        for (int c4 = 0; c4 < 16; c4++) {
            ulonglong2 t = cfp[iphys * 16 + c4];
            rowp[2 * c4]     = t.x;
            rowp[2 * c4 + 1] = t.y;
        }

        int jmin = iv - jb;   // valid pairs need local j > jmin

        __syncthreads();      // protect Js from previous job's readers
        #pragma unroll
        for (int q0 = 0; q0 < JT * 16; q0 += 64) {
            int q = q0 + tid;
            int r = q >> 4;
            int jv = jb + r;
            int jc = 1, jstart = 0;
            #pragma unroll
            for (int cc = 2; cc < NC; cc++)
                if (jv >= pre[cc]) { jc = cc; jstart = pre[cc]; }
            int jp = (jv < nv) ? ((jc - 1) * CAP + (jv - jstart)) : 0;
            Js[r][q & 15] = cfp[jp * 16 + (q & 15)];
        }
        __syncthreads();

        if (ci > 0) {
            #pragma unroll
            for (int c = 1; c < NC; c++) {
                if (c == ci) continue;
                int rs = max(pre[c] - jb, 0);
                int re = min(pre[c + 1] - jb, JT);
                int j = max(rs, jmin + 1);      // skip sub-diagonal j entirely
                if (j >= re) continue;
                float rsum = 0.f;
                for (; j + 1 < re; j += 2) {
                    u64 a0 = 0ull, a1 = 0ull, a2 = 0ull, a3 = 0ull;
                    u64 b0 = 0ull, b1 = 0ull, b2 = 0ull, b3 = 0ull;
                    #pragma unroll
                    for (int c4 = 0; c4 < 8; c4++) {
                        ulonglong2 p0 = Js[j][c4];
                        ulonglong2 p1 = Js[j][c4 + 8];
                        ulonglong2 q0 = Js[j + 1][c4];
                        ulonglong2 q1 = Js[j + 1][c4 + 8];
                        FMA2(a0, rowp[2 * c4],            p0.x);
                        FMA2(a1, rowp[2 * c4 + 1],        p0.y);
                        FMA2(a2, rowp[2 * (c4 + 8)],      p1.x);
                        FMA2(a3, rowp[2 * (c4 + 8) + 1],  p1.y);
                        FMA2(b0, rowp[2 * c4],            q0.x);
                        FMA2(b1, rowp[2 * c4 + 1],        q0.y);
                        FMA2(b2, rowp[2 * (c4 + 8)],      q1.x);
                        FMA2(b3, rowp[2 * (c4 + 8) + 1],  q1.y);
                    }
                    float s0 = fmaxf((sum2(a0) + sum2(a1)) + (sum2(a2) + sum2(a3)), 0.f);
                    float s1 = fmaxf((sum2(b0) + sum2(b1)) + (sum2(b2) + sum2(b3)), 0.f);
                    rsum += s0 + s1;
                }
                if (j < re) {
                    u64 a0 = 0ull, a1 = 0ull, a2 = 0ull, a3 = 0ull;
                    #pragma unroll
                    for (int c4 = 0; c4 < 8; c4++) {
                        ulonglong2 p0 = Js[j][c4];
                        ulonglong2 p1 = Js[j][c4 + 8];
                        FMA2(a0, rowp[2 * c4],            p0.x);
                        FMA2(a1, rowp[2 * c4 + 1],        p0.y);
                        FMA2(a2, rowp[2 * (c4 + 8)],      p1.x);
                        FMA2(a3, rowp[2 * (c4 + 8) + 1],  p1.y);
                    }
                    rsum += fmaxf((sum2(a0) + sum2(a1)) + (sum2(a2) + sum2(a3)), 0.f);
                }
                if (rsum > 0.f) {
                    int lo = min(ci, c), hi = max(ci, c);
                    atomicAdd(&scross[lo * NC + hi], rsum);
                }
            }
        }
    }
    __syncthreads();
    for (int i = tid; i < NC * NC; i += 64)
        if (scross[i] != 0.f) atomicAdd(&g_cross[i], scross[i]);
    // exit — kernel boundary orders KC
}

// ---- KC: finalize + reset (single tiny block) ----
__global__ void __launch_bounds__(128) kc_final(float* __restrict__ out) {
    __shared__ float red[128];
    __shared__ int s_pre[NC + 1];
    int tid = threadIdx.x;

    if (tid == 0) {
        int acc = 0;
        #pragma unroll
        for (int c = 1; c < NC; c++) {
            s_pre[c] = acc;
            acc += g_fill[c] - (c - 1) * CAP;
        }
        s_pre[NC] = acc;
    }
    __syncthreads();

    float acc = 0.f;
    if (tid >= 1 && tid < NC) {
        float cnt = (float)(s_pre[tid + 1] - s_pre[tid]);
        float quad = 0.f;
        #pragma unroll
        for (int d = 0; d < DIM; d++) {
            float vv = g_sum[tid * DIM + d];
            quad += vv * vv;
        }
        float npairs = cnt * (cnt - 1.0f) * 0.5f;
        if (npairs > 0.f)
            acc += 1.0f - ((quad - cnt) * 0.5f) / npairs;
    }
    for (int idx = tid; idx < NC * NC; idx += 128) {
        int a = idx / NC, b = idx % NC;
        if (a >= 1 && b > a) {
            float ca = (float)(s_pre[a + 1] - s_pre[a]);
            float cb = (float)(s_pre[b + 1] - s_pre[b]);
            float den = ca * cb;
            if (den > 0.f) acc += g_cross[a * NC + b] / den;
        }
    }
    red[tid] = acc;
    __syncthreads();
    #pragma unroll
    for (int o = 64; o > 0; o >>= 1) {
        if (tid < o) red[tid] += red[tid + o];
        __syncthreads();
    }
    if (tid == 0) out[0] = red[0];

    // reset for next graph replay
    __syncthreads();
    if (tid >= 1 && tid < NC) g_fill[tid] = (tid - 1) * CAP;
    if (tid < NC * NC) g_cross[tid] = 0.f;
    for (int i = tid; i < NC * DIM; i += 128) g_sum[i] = 0.f;
}

extern "C" void kernel_launch(void* const* d_in, const int* in_sizes, int n_in,
                              void* d_out, int out_size) {
    const int*   labels = nullptr;
    const float* feats  = nullptr;
    const float* scores = nullptr;
    for (int i = 0; i < n_in; i++) {
        if (in_sizes[i] == NPTS)            labels = (const int*)d_in[i];
        else if (in_sizes[i] == NPTS * DIM) feats  = (const float*)d_in[i];
        else if (in_sizes[i] == NPTS * NC)  scores = (const float*)d_in[i];
    }
    float* out = (float*)d_out;

    ka_classify_scatter<<<KAB, 128>>>(labels, feats, scores);
    kb_pairs<<<NB3, 64>>>();
    kc_final<<<1, 128>>>(out);
}